// round 1
// baseline (speedup 1.0000x reference)
#include <cuda_runtime.h>
#include <cuda_bf16.h>

// Problem constants
#define BB 4
#define NN 16384
#define SS 2048
#define CC 64
#define NSAMPLE 32
#define KTOT 33          // 1 (fps) + 32 (ball)
#define OUTC 70          // 3 raw_xyz + 3 grouped_xyz + 64 features

// Scratch: features transposed to (B, N, C) so each point's channels are contiguous (256B).
__device__ float g_ftr_t[(size_t)BB * NN * CC];

// ---------------------------------------------------------------------------
// Kernel 1: transpose features (B, C, N) -> (B, N, C), tiled via smem.
// ---------------------------------------------------------------------------
__global__ void transpose_feat_kernel(const float* __restrict__ in, float* __restrict__ out) {
    __shared__ float tile[32][33];
    int b  = blockIdx.z;
    int n0 = blockIdx.x * 32;
    int c0 = blockIdx.y * 32;

    int n = n0 + threadIdx.x;        // coalesced read along N
    int c = c0 + threadIdx.y;
    tile[threadIdx.y][threadIdx.x] = in[((size_t)b * CC + c) * NN + n];
    __syncthreads();

    int n2 = n0 + threadIdx.y;
    int c2 = c0 + threadIdx.x;       // coalesced write along C
    out[((size_t)b * NN + n2) * CC + c2] = tile[threadIdx.x][threadIdx.y];
}

// ---------------------------------------------------------------------------
// Kernel 2: fused ball query + group. One warp per query point.
//  - warp scans xyz in 32-point chunks, ballot+popc collects first 32 hit
//    indices in ascending order, early exit once 32 found.
//  - xyz channels written directly (coalesced across k lanes).
//  - feature gather: per id, 64 channels are 256B contiguous in g_ftr_t;
//    staged in padded smem then written out channel-major, coalesced.
// ---------------------------------------------------------------------------
#define WPB 4   // warps per block

__global__ __launch_bounds__(WPB * 32)
void qag_kernel(const float* __restrict__ xyz,      // (B, N, 3)
                const float* __restrict__ new_xyz,  // (B, S, 3)
                const float* __restrict__ ftr_t,    // (B, N, C) transposed
                const int*   __restrict__ fps,      // (B, S)
                float*       __restrict__ out)      // (B, 70, S, 33)
{
    __shared__ int   s_idx[WPB][KTOT];
    __shared__ float s_stage[WPB][KTOT][CC + 1];   // +1 pad: conflict-free column reads

    const int warp = threadIdx.x >> 5;
    const int lane = threadIdx.x & 31;
    const int q    = blockIdx.x * WPB + warp;      // global query id, grid sized exactly
    const int b    = q / SS;
    const int s    = q % SS;

    // Query point (each lane loads; L1 broadcast)
    const float qx = new_xyz[q * 3 + 0];
    const float qy = new_xyz[q * 3 + 1];
    const float qz = new_xyz[q * 3 + 2];

    const float* __restrict__ px = xyz + (size_t)b * NN * 3;
    const float R2 = 0.01f;   // float(0.1*0.1 in double) == 0.01f

    // ---- ball query scan ----
    int count = 0;
    for (int base = 0; base < NN; base += 32) {
        const int i = base + lane;
        const float dx = __fsub_rn(qx, px[i * 3 + 0]);
        const float dy = __fsub_rn(qy, px[i * 3 + 1]);
        const float dz = __fsub_rn(qz, px[i * 3 + 2]);
        // exact JAX order: (dx^2 + dy^2) + dz^2, no FMA contraction
        const float d2 = __fadd_rn(__fadd_rn(__fmul_rn(dx, dx), __fmul_rn(dy, dy)),
                                   __fmul_rn(dz, dz));
        const bool hit = d2 < R2;
        const unsigned m = __ballot_sync(0xffffffffu, hit);
        const int pos = count + __popc(m & ((1u << lane) - 1u));
        if (hit && pos < NSAMPLE) s_idx[warp][1 + pos] = i;
        count += __popc(m);
        if (count >= NSAMPLE) break;   // warp-uniform
    }
    __syncwarp();

    const int cnt = count < NSAMPLE ? count : NSAMPLE;
    const int first = (cnt > 0) ? s_idx[warp][1] : 0;
    if (lane >= cnt) s_idx[warp][1 + lane] = first;   // pad with first hit (or 0)
    if (lane == 0)   s_idx[warp][0] = fps[q];
    __syncwarp();

    // ---- xyz channels (0..5) ----
    const size_t CS    = (size_t)SS * KTOT;               // channel stride in out
    const size_t obase = ((size_t)b * OUTC * SS + s) * KTOT;
    #pragma unroll
    for (int k = lane; k < KTOT; k += 32) {
        const int id = s_idx[warp][k];
        const float x = px[id * 3 + 0];
        const float y = px[id * 3 + 1];
        const float z = px[id * 3 + 2];
        const size_t o = obase + k;
        out[o]          = x;
        out[o + CS]     = y;
        out[o + 2 * CS] = z;
        out[o + 3 * CS] = __fsub_rn(x, qx);
        out[o + 4 * CS] = __fsub_rn(y, qy);
        out[o + 5 * CS] = __fsub_rn(z, qz);
    }

    // ---- feature gather into smem stage (coalesced 128B loads per id) ----
    const float* __restrict__ fb = ftr_t + (size_t)b * NN * CC;
    #pragma unroll 4
    for (int k = 0; k < KTOT; k++) {
        const int id = s_idx[warp][k];
        const float* __restrict__ fr = fb + (size_t)id * CC;
        s_stage[warp][k][lane]      = fr[lane];
        s_stage[warp][k][lane + 32] = fr[lane + 32];
    }
    __syncwarp();

    // ---- write features out (channels 6..69), coalesced across k ----
    const size_t fbase = obase + 6 * CS;
    #pragma unroll 4
    for (int c = 0; c < CC; c++) {
        const size_t oc = fbase + (size_t)c * CS;
        // lanes 0..31 cover k=0..31; second pass lane 0 covers k=32
        out[oc + lane] = s_stage[warp][lane][c];
        if (lane == 0) out[oc + 32] = s_stage[warp][32][c];
    }
}

// ---------------------------------------------------------------------------
// Launch
// ---------------------------------------------------------------------------
extern "C" void kernel_launch(void* const* d_in, const int* in_sizes, int n_in,
                              void* d_out, int out_size) {
    const float* xyz      = (const float*)d_in[0];   // (B, N, 3)
    const float* new_xyz  = (const float*)d_in[1];   // (B, S, 3)
    const float* features = (const float*)d_in[2];   // (B, C, N)
    const int*   fps_idx  = (const int*)  d_in[3];   // (B, S)
    float*       out      = (float*)d_out;           // (B, 70, S, 33)

    float* ftr_t = nullptr;
    cudaGetSymbolAddress((void**)&ftr_t, g_ftr_t);

    // 1) transpose features -> (B, N, C)
    transpose_feat_kernel<<<dim3(NN / 32, CC / 32, BB), dim3(32, 32)>>>(features, ftr_t);

    // 2) fused ball query + group: one warp per query
    const int nq = BB * SS;                 // 8192
    qag_kernel<<<nq / WPB, WPB * 32>>>(xyz, new_xyz, ftr_t, fps_idx, out);
}

// round 11
// speedup vs baseline: 3.3419x; 3.3419x over previous
#include <cuda_runtime.h>
#include <cuda_bf16.h>

// Problem constants
#define BB 4
#define NN 16384
#define SS 2048
#define CC 64
#define NSAMPLE 32
#define KTOT 33          // 1 (fps) + 32 (ball)
#define OUTC 70          // 3 raw_xyz + 3 grouped_xyz + 64 features

// Grid constants
#define GRD 10           // cells per dim (cell size = 0.1 = RADIUS)
#define NCELLS 1000      // per batch
#define NCELLS_PAD 4096  // BB*NCELLS=4000 padded to scan width
#define CAP 192          // per-query hit buffer (mean ~69, 14 sigma margin)

// Scratch (device globals; no runtime allocation allowed)
__device__ float g_ftr_t[(size_t)BB * NN * CC];   // features transposed (B,N,C)
__device__ float g_sx[BB * NN];                   // xyz SoA (index order)
__device__ float g_sy[BB * NN];
__device__ float g_sz[BB * NN];
__device__ int   g_cellid[BB * NN];               // global cell id per point
__device__ int   g_cnt[NCELLS_PAD];               // per-cell counts
__device__ int   g_off[NCELLS_PAD + 1];           // exclusive offsets
__device__ int   g_cur[NCELLS_PAD];               // scatter cursors
__device__ float g_gx[BB * NN];                   // grid-ordered coords
__device__ float g_gy[BB * NN];
__device__ float g_gz[BB * NN];
__device__ int   g_gid[BB * NN];                  // grid-ordered local point index

__device__ __forceinline__ int cell1d(float v) {
    int c = __float2int_rd(v * 10.0f);
    return min(GRD - 1, max(0, c));
}

// ---------------------------------------------------------------------------
// Kernel 1: transpose features (B, C, N) -> (B, N, C), tiled via smem.
// ---------------------------------------------------------------------------
__global__ void transpose_feat_kernel(const float* __restrict__ in, float* __restrict__ out) {
    __shared__ float tile[32][33];
    int b  = blockIdx.z;
    int n0 = blockIdx.x * 32;
    int c0 = blockIdx.y * 32;

    int n = n0 + threadIdx.x;
    int c = c0 + threadIdx.y;
    tile[threadIdx.y][threadIdx.x] = in[((size_t)b * CC + c) * NN + n];
    __syncthreads();

    int n2 = n0 + threadIdx.y;
    int c2 = c0 + threadIdx.x;
    out[((size_t)b * NN + n2) * CC + c2] = tile[threadIdx.x][threadIdx.y];
}

// ---------------------------------------------------------------------------
// Kernel 2: zero the cell counts.
// ---------------------------------------------------------------------------
__global__ void zero_cnt_kernel() {
    int i = blockIdx.x * blockDim.x + threadIdx.x;
    if (i < NCELLS_PAD) g_cnt[i] = 0;
}

// ---------------------------------------------------------------------------
// Kernel 3: xyz -> SoA + cell id + per-cell count.
// ---------------------------------------------------------------------------
__global__ void soa_count_kernel(const float* __restrict__ xyz) {
    int p = blockIdx.x * blockDim.x + threadIdx.x;   // 0 .. BB*NN-1
    float x = xyz[p * 3 + 0];
    float y = xyz[p * 3 + 1];
    float z = xyz[p * 3 + 2];
    g_sx[p] = x; g_sy[p] = y; g_sz[p] = z;
    int b = p / NN;
    int cell = (cell1d(z) * GRD + cell1d(y)) * GRD + cell1d(x);
    int gc = b * NCELLS + cell;
    g_cellid[p] = gc;
    atomicAdd(&g_cnt[gc], 1);
}

// ---------------------------------------------------------------------------
// Kernel 4: exclusive scan over 4096 counts (1 block, 1024 threads, 4/thread).
// ---------------------------------------------------------------------------
__global__ void scan_kernel() {
    __shared__ int part[1024];
    int t = threadIdx.x;
    int v[4]; int s = 0;
    #pragma unroll
    for (int i = 0; i < 4; i++) { v[i] = g_cnt[t * 4 + i]; s += v[i]; }
    part[t] = s;
    __syncthreads();
    // Hillis-Steele inclusive scan over the 1024 partials
    for (int d = 1; d < 1024; d <<= 1) {
        int x = (t >= d) ? part[t - d] : 0;
        __syncthreads();
        part[t] += x;
        __syncthreads();
    }
    int base = (t > 0) ? part[t - 1] : 0;
    #pragma unroll
    for (int i = 0; i < 4; i++) {
        g_off[t * 4 + i] = base;
        g_cur[t * 4 + i] = base;
        base += v[i];
    }
    if (t == 1023) g_off[NCELLS_PAD] = base;   // = BB*NN
}

// ---------------------------------------------------------------------------
// Kernel 5: scatter points into grid order (coords + local id).
// Within-cell order is nondeterministic but never observable in the output
// (selection is by point index).
// ---------------------------------------------------------------------------
__global__ void scatter_kernel() {
    int p = blockIdx.x * blockDim.x + threadIdx.x;
    int gc  = g_cellid[p];
    int pos = atomicAdd(&g_cur[gc], 1);
    g_gx[pos]  = g_sx[p];
    g_gy[pos]  = g_sy[p];
    g_gz[pos]  = g_sz[p];
    g_gid[pos] = p % NN;                 // local (per-batch) index
}

// ---------------------------------------------------------------------------
// Kernel 6: fused grid ball query + group. One warp per query point.
// ---------------------------------------------------------------------------
#define WPB 4   // warps per block
#define HC  32  // channels per staging pass
#define TSEL ((CAP + 31) / 32)

__global__ __launch_bounds__(WPB * 32)
void qag_kernel(const float* __restrict__ new_xyz,  // (B, S, 3)
                const float* __restrict__ ftr_t,    // (B, N, C) transposed
                const int*   __restrict__ fps,      // (B, S)
                float*       __restrict__ out)      // (B, 70, S, 33)
{
    __shared__ int   s_idx[WPB][KTOT];
    __shared__ int   s_hits[WPB][CAP];
    __shared__ float s_stage[WPB][KTOT][HC + 1];

    const int warp = threadIdx.x >> 5;
    const int lane = threadIdx.x & 31;
    const int q    = blockIdx.x * WPB + warp;
    const int b    = q / SS;
    const int s    = q % SS;

    const float qx = new_xyz[q * 3 + 0];
    const float qy = new_xyz[q * 3 + 1];
    const float qz = new_xyz[q * 3 + 2];

    const float R2 = 0.01f;                        // float(0.1*0.1) == 0.01f
    const unsigned lmask = (1u << lane) - 1u;

    // ---- candidate cell ranges (slop absorbs float boundary rounding) ----
    const float SLOP = 0.1f + 1e-6f;
    const int lx = cell1d(__fsub_rn(qx, SLOP)), hx = cell1d(__fadd_rn(qx, SLOP));
    const int ly = cell1d(__fsub_rn(qy, SLOP)), hy = cell1d(__fadd_rn(qy, SLOP));
    const int lz = cell1d(__fsub_rn(qz, SLOP)), hz = cell1d(__fadd_rn(qz, SLOP));

    // ---- grid ball query: collect ALL hit ids (unordered) ----
    int M = 0;
    for (int cz = lz; cz <= hz; cz++) {
        for (int cy = ly; cy <= hy; cy++) {
            // cells [lx..hx] are contiguous -> one merged candidate range
            const int cbase = b * NCELLS + (cz * GRD + cy) * GRD;
            const int s0 = g_off[cbase + lx];
            const int s1 = g_off[cbase + hx + 1];
            for (int jj = s0; jj < s1; jj += 32) {     // warp-uniform trip
                const int j = jj + lane;
                const bool act = j < s1;
                const float x = act ? g_gx[j] : 1e9f;
                const float y = act ? g_gy[j] : 1e9f;
                const float z = act ? g_gz[j] : 1e9f;
                const float dx = __fsub_rn(qx, x);
                const float dy = __fsub_rn(qy, y);
                const float dz = __fsub_rn(qz, z);
                // exact JAX order: (dx^2 + dy^2) + dz^2, no FMA contraction
                const float d2 = __fadd_rn(__fadd_rn(__fmul_rn(dx, dx), __fmul_rn(dy, dy)),
                                           __fmul_rn(dz, dz));
                const bool hit = act && (d2 < R2);
                const unsigned m = __ballot_sync(0xffffffffu, hit);
                const int pos = M + __popc(m & lmask);
                if (hit && pos < CAP) s_hits[warp][pos] = g_gid[j];
                M += __popc(m);
            }
        }
    }
    __syncwarp();

    int count;   // total hit count (for cnt/pad logic)
    if (M <= CAP) {
        count = M;
        // ---- exact selection of the 32 smallest ids (rank-based) ----
        const int tcnt = (M + 31) >> 5;
        int mine[TSEL], rank[TSEL];
        #pragma unroll
        for (int t = 0; t < TSEL; t++) {
            const int i = lane + 32 * t;
            mine[t] = (t < tcnt && i < M) ? s_hits[warp][i] : 0x7fffffff;
            rank[t] = 0;
        }
        for (int e = 0; e < M; e++) {
            const int v = s_hits[warp][e];       // LDS broadcast
            #pragma unroll
            for (int t = 0; t < TSEL; t++) rank[t] += (v < mine[t]);
        }
        #pragma unroll
        for (int t = 0; t < TSEL; t++) {
            const int i = lane + 32 * t;
            if (i < M && rank[t] < NSAMPLE) s_idx[warp][1 + rank[t]] = mine[t];
        }
    } else {
        // ---- fallback (buffer overflow; effectively unreachable): linear scan ----
        const float* __restrict__ bx = g_sx + b * NN;
        const float* __restrict__ by = g_sy + b * NN;
        const float* __restrict__ bz = g_sz + b * NN;
        count = 0;
        for (int base = 0; base < NN; base += 32) {
            const int i = base + lane;
            const float dx = __fsub_rn(qx, bx[i]);
            const float dy = __fsub_rn(qy, by[i]);
            const float dz = __fsub_rn(qz, bz[i]);
            const float d2 = __fadd_rn(__fadd_rn(__fmul_rn(dx, dx), __fmul_rn(dy, dy)),
                                       __fmul_rn(dz, dz));
            const bool hit = d2 < R2;
            const unsigned m = __ballot_sync(0xffffffffu, hit);
            const int pos = count + __popc(m & lmask);
            if (hit && pos < NSAMPLE) s_idx[warp][1 + pos] = i;
            count += __popc(m);
            if (count >= NSAMPLE) break;
        }
    }
    __syncwarp();

    const int cnt = count < NSAMPLE ? count : NSAMPLE;
    const int first = (cnt > 0) ? s_idx[warp][1] : 0;
    if (lane >= cnt) s_idx[warp][1 + lane] = first;   // pad with first hit (or 0)
    if (lane == 0)   s_idx[warp][0] = fps[q];
    __syncwarp();

    // ---- xyz channels (0..5) ----
    const float* __restrict__ bx = g_sx + b * NN;
    const float* __restrict__ by = g_sy + b * NN;
    const float* __restrict__ bz = g_sz + b * NN;
    const size_t CS    = (size_t)SS * KTOT;
    const size_t obase = ((size_t)b * OUTC * SS + s) * KTOT;
    #pragma unroll
    for (int k = lane; k < KTOT; k += 32) {
        const int id = s_idx[warp][k];
        const float x = bx[id];
        const float y = by[id];
        const float z = bz[id];
        const size_t o = obase + k;
        out[o]          = x;
        out[o + CS]     = y;
        out[o + 2 * CS] = z;
        out[o + 3 * CS] = __fsub_rn(x, qx);
        out[o + 4 * CS] = __fsub_rn(y, qy);
        out[o + 5 * CS] = __fsub_rn(z, qz);
    }

    // ---- feature gather + transpose: 2 passes of 32 channels ----
    const float* __restrict__ fb = ftr_t + (size_t)b * NN * CC;
    const size_t fbase = obase + 6 * CS;

    #pragma unroll
    for (int half = 0; half < 2; half++) {
        const int c0 = half * HC;
        #pragma unroll 4
        for (int k = 0; k < KTOT; k++) {
            const int id = s_idx[warp][k];
            s_stage[warp][k][lane] = fb[(size_t)id * CC + c0 + lane];
        }
        __syncwarp();
        #pragma unroll 4
        for (int c = 0; c < HC; c++) {
            const size_t oc = fbase + (size_t)(c0 + c) * CS;
            out[oc + lane] = s_stage[warp][lane][c];
            if (lane == 0) out[oc + 32] = s_stage[warp][32][c];
        }
        __syncwarp();
    }
}

// ---------------------------------------------------------------------------
// Launch
// ---------------------------------------------------------------------------
extern "C" void kernel_launch(void* const* d_in, const int* in_sizes, int n_in,
                              void* d_out, int out_size) {
    const float* xyz      = (const float*)d_in[0];   // (B, N, 3)
    const float* new_xyz  = (const float*)d_in[1];   // (B, S, 3)
    const float* features = (const float*)d_in[2];   // (B, C, N)
    const int*   fps_idx  = (const int*)  d_in[3];   // (B, S)
    float*       out      = (float*)d_out;           // (B, 70, S, 33)

    float* ftr_t = nullptr;
    cudaGetSymbolAddress((void**)&ftr_t, g_ftr_t);

    // prep
    transpose_feat_kernel<<<dim3(NN / 32, CC / 32, BB), dim3(32, 32)>>>(features, ftr_t);
    zero_cnt_kernel<<<NCELLS_PAD / 256, 256>>>();
    soa_count_kernel<<<(BB * NN) / 256, 256>>>(xyz);
    scan_kernel<<<1, 1024>>>();
    scatter_kernel<<<(BB * NN) / 256, 256>>>();

    // fused grid ball query + group: one warp per query
    const int nq = BB * SS;                 // 8192
    qag_kernel<<<nq / WPB, WPB * 32>>>(new_xyz, ftr_t, fps_idx, out);
}

// round 13
// speedup vs baseline: 3.4354x; 1.0280x over previous
#include <cuda_runtime.h>
#include <cuda_bf16.h>

// Problem constants
#define BB 4
#define NN 16384
#define SS 2048
#define CC 64
#define NSAMPLE 32
#define KTOT 33          // 1 (fps) + 32 (ball)
#define OUTC 70          // 3 raw_xyz + 3 grouped_xyz + 64 features

// Grid constants
#define GRD 10           // cells per dim (cell size = 0.1 = RADIUS)
#define NCELLS 1000      // per batch
#define NCELLS_PAD 4096  // BB*NCELLS=4000 padded to scan width
#define CAP 192          // per-query hit buffer (mean ~69, 14 sigma margin)

// Scratch (device globals; no runtime allocation allowed)
__device__ float g_ftr_t[(size_t)BB * NN * CC];   // features transposed (B,N,C)
__device__ float g_sx[BB * NN];                   // xyz SoA (index order)
__device__ float g_sy[BB * NN];
__device__ float g_sz[BB * NN];
__device__ int   g_cellid[BB * NN];               // global cell id per point
__device__ int   g_cnt[NCELLS_PAD];               // per-cell counts
__device__ int   g_off[NCELLS_PAD + 1];           // exclusive offsets
__device__ int   g_cur[NCELLS_PAD];               // scatter cursors
__device__ float g_gx[BB * NN];                   // grid-ordered coords
__device__ float g_gy[BB * NN];
__device__ float g_gz[BB * NN];
__device__ int   g_gid[BB * NN];                  // grid-ordered local point index

__device__ __forceinline__ int cell1d(float v) {
    int c = __float2int_rd(v * 10.0f);
    return min(GRD - 1, max(0, c));
}

// ---------------------------------------------------------------------------
// Kernel 1: transpose features (B, C, N) -> (B, N, C), tiled via smem.
// ---------------------------------------------------------------------------
__global__ void transpose_feat_kernel(const float* __restrict__ in, float* __restrict__ out) {
    __shared__ float tile[32][33];
    int b  = blockIdx.z;
    int n0 = blockIdx.x * 32;
    int c0 = blockIdx.y * 32;

    int n = n0 + threadIdx.x;
    int c = c0 + threadIdx.y;
    tile[threadIdx.y][threadIdx.x] = in[((size_t)b * CC + c) * NN + n];
    __syncthreads();

    int n2 = n0 + threadIdx.y;
    int c2 = c0 + threadIdx.x;
    out[((size_t)b * NN + n2) * CC + c2] = tile[threadIdx.x][threadIdx.y];
}

// ---------------------------------------------------------------------------
// Kernel 2: zero the cell counts.
// ---------------------------------------------------------------------------
__global__ void zero_cnt_kernel() {
    int i = blockIdx.x * blockDim.x + threadIdx.x;
    if (i < NCELLS_PAD) g_cnt[i] = 0;
}

// ---------------------------------------------------------------------------
// Kernel 3: xyz -> SoA + cell id + per-cell count.
// ---------------------------------------------------------------------------
__global__ void soa_count_kernel(const float* __restrict__ xyz) {
    int p = blockIdx.x * blockDim.x + threadIdx.x;   // 0 .. BB*NN-1
    float x = xyz[p * 3 + 0];
    float y = xyz[p * 3 + 1];
    float z = xyz[p * 3 + 2];
    g_sx[p] = x; g_sy[p] = y; g_sz[p] = z;
    int b = p / NN;
    int cell = (cell1d(z) * GRD + cell1d(y)) * GRD + cell1d(x);
    int gc = b * NCELLS + cell;
    g_cellid[p] = gc;
    atomicAdd(&g_cnt[gc], 1);
}

// ---------------------------------------------------------------------------
// Kernel 4: exclusive scan over 4096 counts — shuffle-based, 2 barriers total
// (was Hillis-Steele with 20 block barriers -> 7us; this should be ~1.5us).
// ---------------------------------------------------------------------------
__global__ void scan_kernel() {
    __shared__ int wsum[32];
    const int t    = threadIdx.x;       // 0..1023
    const int lane = t & 31;
    const int w    = t >> 5;

    int v[4]; int s = 0;
    #pragma unroll
    for (int i = 0; i < 4; i++) { v[i] = g_cnt[t * 4 + i]; s += v[i]; }

    // inclusive warp scan of per-thread sums
    int sc = s;
    #pragma unroll
    for (int d = 1; d < 32; d <<= 1) {
        int x = __shfl_up_sync(0xffffffffu, sc, d);
        if (lane >= d) sc += x;
    }
    if (lane == 31) wsum[w] = sc;
    __syncthreads();

    // warp 0 scans the 32 warp totals (inclusive)
    if (w == 0) {
        int ws = wsum[lane];
        #pragma unroll
        for (int d = 1; d < 32; d <<= 1) {
            int x = __shfl_up_sync(0xffffffffu, ws, d);
            if (lane >= d) ws += x;
        }
        wsum[lane] = ws;
    }
    __syncthreads();

    int base = (sc - s) + (w > 0 ? wsum[w - 1] : 0);   // exclusive prefix
    #pragma unroll
    for (int i = 0; i < 4; i++) {
        g_off[t * 4 + i] = base;
        g_cur[t * 4 + i] = base;
        base += v[i];
    }
    if (t == 1023) g_off[NCELLS_PAD] = base;   // = BB*NN
}

// ---------------------------------------------------------------------------
// Kernel 5: scatter points into grid order (coords + local id).
// Within-cell order is nondeterministic but never observable in the output
// (selection is by point index).
// ---------------------------------------------------------------------------
__global__ void scatter_kernel() {
    int p = blockIdx.x * blockDim.x + threadIdx.x;
    int gc  = g_cellid[p];
    int pos = atomicAdd(&g_cur[gc], 1);
    g_gx[pos]  = g_sx[p];
    g_gy[pos]  = g_sy[p];
    g_gz[pos]  = g_sz[p];
    g_gid[pos] = p % NN;                 // local (per-batch) index
}

// ---------------------------------------------------------------------------
// Kernel 6: fused grid ball query + group. One warp per query point.
//  - all candidate-range bounds fetched in ONE parallel round (lanes 0..nr-1),
//    then broadcast via shuffle: removes ~8 serialized L2 round-trips/query.
// ---------------------------------------------------------------------------
#define WPB 4   // warps per block
#define HC  32  // channels per staging pass
#define TSEL ((CAP + 31) / 32)

__global__ __launch_bounds__(WPB * 32)
void qag_kernel(const float* __restrict__ new_xyz,  // (B, S, 3)
                const float* __restrict__ ftr_t,    // (B, N, C) transposed
                const int*   __restrict__ fps,      // (B, S)
                float*       __restrict__ out)      // (B, 70, S, 33)
{
    __shared__ int   s_idx[WPB][KTOT];
    __shared__ int   s_hits[WPB][CAP];
    __shared__ float s_stage[WPB][KTOT][HC + 1];

    const int warp = threadIdx.x >> 5;
    const int lane = threadIdx.x & 31;
    const int q    = blockIdx.x * WPB + warp;
    const int b    = q / SS;
    const int s    = q % SS;

    const float qx = new_xyz[q * 3 + 0];
    const float qy = new_xyz[q * 3 + 1];
    const float qz = new_xyz[q * 3 + 2];

    const float R2 = 0.01f;                        // float(0.1*0.1) == 0.01f
    const unsigned lmask = (1u << lane) - 1u;

    // ---- candidate cell ranges (slop absorbs float boundary rounding) ----
    const float SLOP = 0.1f + 1e-6f;
    const int lx = cell1d(__fsub_rn(qx, SLOP)), hx = cell1d(__fadd_rn(qx, SLOP));
    const int ly = cell1d(__fsub_rn(qy, SLOP)), hy = cell1d(__fadd_rn(qy, SLOP));
    const int lz = cell1d(__fsub_rn(qz, SLOP)), hz = cell1d(__fadd_rn(qz, SLOP));

    // ---- fetch ALL (s0,s1) range bounds in parallel (one lane per range) ----
    const int ny = hy - ly + 1;
    const int nr = (hz - lz + 1) * ny;             // <= 9
    int s0r = 0, s1r = 0;
    if (lane < nr) {
        const int cz = lz + lane / ny;
        const int cy = ly + lane % ny;
        const int cbase = b * NCELLS + (cz * GRD + cy) * GRD;
        s0r = g_off[cbase + lx];                   // cells [lx..hx] contiguous
        s1r = g_off[cbase + hx + 1];
    }

    // ---- grid ball query: collect ALL hit ids (unordered) ----
    int M = 0;
    for (int r = 0; r < nr; r++) {
        const int s0 = __shfl_sync(0xffffffffu, s0r, r);
        const int s1 = __shfl_sync(0xffffffffu, s1r, r);
        for (int jj = s0; jj < s1; jj += 32) {     // warp-uniform trip
            const int j = jj + lane;
            const bool act = j < s1;
            const float x = act ? g_gx[j] : 1e9f;
            const float y = act ? g_gy[j] : 1e9f;
            const float z = act ? g_gz[j] : 1e9f;
            const float dx = __fsub_rn(qx, x);
            const float dy = __fsub_rn(qy, y);
            const float dz = __fsub_rn(qz, z);
            // exact JAX order: (dx^2 + dy^2) + dz^2, no FMA contraction
            const float d2 = __fadd_rn(__fadd_rn(__fmul_rn(dx, dx), __fmul_rn(dy, dy)),
                                       __fmul_rn(dz, dz));
            const bool hit = act && (d2 < R2);
            const unsigned m = __ballot_sync(0xffffffffu, hit);
            const int pos = M + __popc(m & lmask);
            if (hit && pos < CAP) s_hits[warp][pos] = g_gid[j];
            M += __popc(m);
        }
    }
    __syncwarp();

    int count;   // total hit count (for cnt/pad logic)
    if (M <= CAP) {
        count = M;
        // ---- exact selection of the 32 smallest ids (rank-based) ----
        const int tcnt = (M + 31) >> 5;
        int mine[TSEL], rank[TSEL];
        #pragma unroll
        for (int t = 0; t < TSEL; t++) {
            const int i = lane + 32 * t;
            mine[t] = (t < tcnt && i < M) ? s_hits[warp][i] : 0x7fffffff;
            rank[t] = 0;
        }
        for (int e = 0; e < M; e++) {
            const int v = s_hits[warp][e];       // LDS broadcast
            #pragma unroll
            for (int t = 0; t < TSEL; t++) rank[t] += (v < mine[t]);
        }
        #pragma unroll
        for (int t = 0; t < TSEL; t++) {
            const int i = lane + 32 * t;
            if (i < M && rank[t] < NSAMPLE) s_idx[warp][1 + rank[t]] = mine[t];
        }
    } else {
        // ---- fallback (buffer overflow; effectively unreachable): linear scan ----
        const float* __restrict__ bx = g_sx + b * NN;
        const float* __restrict__ by = g_sy + b * NN;
        const float* __restrict__ bz = g_sz + b * NN;
        count = 0;
        for (int base = 0; base < NN; base += 32) {
            const int i = base + lane;
            const float dx = __fsub_rn(qx, bx[i]);
            const float dy = __fsub_rn(qy, by[i]);
            const float dz = __fsub_rn(qz, bz[i]);
            const float d2 = __fadd_rn(__fadd_rn(__fmul_rn(dx, dx), __fmul_rn(dy, dy)),
                                       __fmul_rn(dz, dz));
            const bool hit = d2 < R2;
            const unsigned m = __ballot_sync(0xffffffffu, hit);
            const int pos = count + __popc(m & lmask);
            if (hit && pos < NSAMPLE) s_idx[warp][1 + pos] = i;
            count += __popc(m);
            if (count >= NSAMPLE) break;
        }
    }
    __syncwarp();

    const int cnt = count < NSAMPLE ? count : NSAMPLE;
    const int first = (cnt > 0) ? s_idx[warp][1] : 0;
    if (lane >= cnt) s_idx[warp][1 + lane] = first;   // pad with first hit (or 0)
    if (lane == 0)   s_idx[warp][0] = fps[q];
    __syncwarp();

    // ---- xyz channels (0..5) ----
    const float* __restrict__ bx = g_sx + b * NN;
    const float* __restrict__ by = g_sy + b * NN;
    const float* __restrict__ bz = g_sz + b * NN;
    const size_t CS    = (size_t)SS * KTOT;
    const size_t obase = ((size_t)b * OUTC * SS + s) * KTOT;
    #pragma unroll
    for (int k = lane; k < KTOT; k += 32) {
        const int id = s_idx[warp][k];
        const float x = bx[id];
        const float y = by[id];
        const float z = bz[id];
        const size_t o = obase + k;
        out[o]          = x;
        out[o + CS]     = y;
        out[o + 2 * CS] = z;
        out[o + 3 * CS] = __fsub_rn(x, qx);
        out[o + 4 * CS] = __fsub_rn(y, qy);
        out[o + 5 * CS] = __fsub_rn(z, qz);
    }

    // ---- feature gather + transpose: 2 passes of 32 channels ----
    const float* __restrict__ fb = ftr_t + (size_t)b * NN * CC;
    const size_t fbase = obase + 6 * CS;

    #pragma unroll
    for (int half = 0; half < 2; half++) {
        const int c0 = half * HC;
        #pragma unroll 4
        for (int k = 0; k < KTOT; k++) {
            const int id = s_idx[warp][k];
            s_stage[warp][k][lane] = fb[(size_t)id * CC + c0 + lane];
        }
        __syncwarp();
        #pragma unroll 4
        for (int c = 0; c < HC; c++) {
            const size_t oc = fbase + (size_t)(c0 + c) * CS;
            out[oc + lane] = s_stage[warp][lane][c];
            if (lane == 0) out[oc + 32] = s_stage[warp][32][c];
        }
        __syncwarp();
    }
}

// ---------------------------------------------------------------------------
// Launch
// ---------------------------------------------------------------------------
extern "C" void kernel_launch(void* const* d_in, const int* in_sizes, int n_in,
                              void* d_out, int out_size) {
    const float* xyz      = (const float*)d_in[0];   // (B, N, 3)
    const float* new_xyz  = (const float*)d_in[1];   // (B, S, 3)
    const float* features = (const float*)d_in[2];   // (B, C, N)
    const int*   fps_idx  = (const int*)  d_in[3];   // (B, S)
    float*       out      = (float*)d_out;           // (B, 70, S, 33)

    float* ftr_t = nullptr;
    cudaGetSymbolAddress((void**)&ftr_t, g_ftr_t);

    // prep
    transpose_feat_kernel<<<dim3(NN / 32, CC / 32, BB), dim3(32, 32)>>>(features, ftr_t);
    zero_cnt_kernel<<<NCELLS_PAD / 256, 256>>>();
    soa_count_kernel<<<(BB * NN) / 256, 256>>>(xyz);
    scan_kernel<<<1, 1024>>>();
    scatter_kernel<<<(BB * NN) / 256, 256>>>();

    // fused grid ball query + group: one warp per query
    const int nq = BB * SS;                 // 8192
    qag_kernel<<<nq / WPB, WPB * 32>>>(new_xyz, ftr_t, fps_idx, out);
}

// round 17
// speedup vs baseline: 3.5905x; 1.0451x over previous
#include <cuda_runtime.h>
#include <cuda_bf16.h>

// Problem constants
#define BB 4
#define NN 16384
#define SS 2048
#define CC 64
#define NSAMPLE 32
#define KTOT 33          // 1 (fps) + 32 (ball)
#define OUTC 70          // 3 raw_xyz + 3 grouped_xyz + 64 features

// Grid constants
#define GRD 10           // cells per dim (cell size = 0.1 = RADIUS)
#define NCELLS 1000      // per batch
#define NCELLS_PAD 4096  // BB*NCELLS=4000 padded to scan width
#define CAP 192          // per-query hit buffer (mean ~69, 14 sigma margin)

// Scratch (device globals; no runtime allocation allowed)
__device__ float g_ftr_t[(size_t)BB * NN * CC];   // features transposed (B,N,C)
__device__ float g_sx[BB * NN];                   // xyz SoA (index order)
__device__ float g_sy[BB * NN];
__device__ float g_sz[BB * NN];
__device__ int   g_cellid[BB * NN];               // global cell id per point
__device__ int   g_cnt[NCELLS_PAD];               // per-cell counts (zeroed by scan after read)
__device__ int   g_off[NCELLS_PAD + 1];           // exclusive offsets
__device__ int   g_cur[NCELLS_PAD];               // scatter cursors
__device__ float g_gx[BB * NN];                   // grid-ordered coords
__device__ float g_gy[BB * NN];
__device__ float g_gz[BB * NN];
__device__ int   g_gid[BB * NN];                  // grid-ordered local point index
__device__ int   g_flag;                          // scan->scatter release flag

__device__ __forceinline__ int cell1d(float v) {
    int c = __float2int_rd(v * 10.0f);
    return min(GRD - 1, max(0, c));
}

// ---------------------------------------------------------------------------
// Kernel A: fused prep.
//  blocks [0, 4096)   : feature transpose (B,C,N)->(B,N,C), tiled via smem
//  blocks [4096, 4160): xyz -> SoA + cell id + per-cell count
//  also resets g_flag for this replay (kernel completes before B launches).
// ---------------------------------------------------------------------------
#define TR_BLOCKS (BB * (NN / 32) * (CC / 32))   // 4096
#define SC_BLOCKS ((BB * NN) / 1024)             // 64

__global__ __launch_bounds__(1024)
void prep_kernel(const float* __restrict__ feat,  // (B, C, N)
                 const float* __restrict__ xyz,   // (B, N, 3)
                 float* __restrict__ ftr_t)       // (B, N, C)
{
    if (blockIdx.x == 0 && threadIdx.x == 0) g_flag = 0;

    if (blockIdx.x < TR_BLOCKS) {
        // ---- transpose tile ----
        __shared__ float tile[32][33];
        const int flat = blockIdx.x;
        const int perb = (NN / 32) * (CC / 32);        // 1024
        const int b    = flat / perb;
        const int rem  = flat % perb;
        const int c0   = (rem / (NN / 32)) * 32;
        const int n0   = (rem % (NN / 32)) * 32;
        const int tx   = threadIdx.x & 31;
        const int ty   = threadIdx.x >> 5;

        tile[ty][tx] = feat[((size_t)b * CC + (c0 + ty)) * NN + (n0 + tx)];
        __syncthreads();
        ftr_t[((size_t)b * NN + (n0 + ty)) * CC + (c0 + tx)] = tile[tx][ty];
    } else {
        // ---- SoA + cell count ----
        const int p = (blockIdx.x - TR_BLOCKS) * 1024 + threadIdx.x;  // < BB*NN
        const float x = xyz[p * 3 + 0];
        const float y = xyz[p * 3 + 1];
        const float z = xyz[p * 3 + 2];
        g_sx[p] = x; g_sy[p] = y; g_sz[p] = z;
        const int b = p / NN;
        const int cell = (cell1d(z) * GRD + cell1d(y)) * GRD + cell1d(x);
        const int gc = b * NCELLS + cell;
        g_cellid[p] = gc;
        atomicAdd(&g_cnt[gc], 1);
    }
}

// ---------------------------------------------------------------------------
// Kernel B: fused scan + scatter. 64 blocks x 1024 threads (all co-resident).
//  block 0: shuffle-scan of 4096 counts -> g_off/g_cur, re-zero g_cnt,
//           fence, release flag. Other blocks spin on the flag (L2 atomic),
//           then all blocks scatter their 1024-point range.
//  Post-spin shared state is only g_cur (accessed atomically -> L2-coherent);
//  coords/cellid were written by kernel A (visible across launch boundary).
// ---------------------------------------------------------------------------
__global__ void __launch_bounds__(1024)
scan_scatter_kernel() {
    if (blockIdx.x == 0) {
        __shared__ int wsum[32];
        const int t    = threadIdx.x;
        const int lane = t & 31;
        const int w    = t >> 5;

        int v[4]; int s = 0;
        #pragma unroll
        for (int i = 0; i < 4; i++) { v[i] = g_cnt[t * 4 + i]; s += v[i]; }
        #pragma unroll
        for (int i = 0; i < 4; i++) g_cnt[t * 4 + i] = 0;   // ready for next replay

        int sc = s;                                  // inclusive warp scan
        #pragma unroll
        for (int d = 1; d < 32; d <<= 1) {
            int x = __shfl_up_sync(0xffffffffu, sc, d);
            if (lane >= d) sc += x;
        }
        if (lane == 31) wsum[w] = sc;
        __syncthreads();
        if (w == 0) {
            int ws = wsum[lane];
            #pragma unroll
            for (int d = 1; d < 32; d <<= 1) {
                int x = __shfl_up_sync(0xffffffffu, ws, d);
                if (lane >= d) ws += x;
            }
            wsum[lane] = ws;
        }
        __syncthreads();

        int base = (sc - s) + (w > 0 ? wsum[w - 1] : 0);   // exclusive prefix
        #pragma unroll
        for (int i = 0; i < 4; i++) {
            g_off[t * 4 + i] = base;
            g_cur[t * 4 + i] = base;
            base += v[i];
        }
        if (t == 1023) g_off[NCELLS_PAD] = base;   // = BB*NN

        __threadfence();
        __syncthreads();
        if (t == 0) atomicExch(&g_flag, 1);        // release
    } else {
        if (threadIdx.x == 0) {
            while (atomicAdd(&g_flag, 0) == 0) { }  // acquire via L2 atomic
        }
        __syncthreads();
    }

    // ---- scatter (all blocks) ----
    const int p  = blockIdx.x * 1024 + threadIdx.x;
    const int gc  = g_cellid[p];
    const int pos = atomicAdd(&g_cur[gc], 1);
    g_gx[pos]  = g_sx[p];
    g_gy[pos]  = g_sy[p];
    g_gz[pos]  = g_sz[p];
    g_gid[pos] = p % NN;                 // local (per-batch) index
}

// ---------------------------------------------------------------------------
// Selection: exact 32-smallest-ids by rank, templated on slot count.
// ---------------------------------------------------------------------------
template <int T>
__device__ __forceinline__ void select_hits(int* __restrict__ s_idx_w,
                                            const int* __restrict__ s_hits_w,
                                            int M, int lane) {
    int mine[T], rank[T];
    #pragma unroll
    for (int t = 0; t < T; t++) {
        const int i = lane + 32 * t;
        mine[t] = (i < M) ? s_hits_w[i] : 0x7fffffff;
        rank[t] = 0;
    }
    for (int e = 0; e < M; e++) {
        const int v = s_hits_w[e];           // LDS broadcast
        #pragma unroll
        for (int t = 0; t < T; t++) rank[t] += (v < mine[t]);
    }
    #pragma unroll
    for (int t = 0; t < T; t++) {
        const int i = lane + 32 * t;
        if (i < M && rank[t] < NSAMPLE) s_idx_w[1 + rank[t]] = mine[t];
    }
}

// ---------------------------------------------------------------------------
// Kernel C: fused grid ball query + group. One warp per query point.
// ---------------------------------------------------------------------------
#define WPB 4   // warps per block
#define HC  32  // channels per staging pass
#define TSEL ((CAP + 31) / 32)

__global__ __launch_bounds__(WPB * 32)
void qag_kernel(const float* __restrict__ new_xyz,  // (B, S, 3)
                const float* __restrict__ ftr_t,    // (B, N, C) transposed
                const int*   __restrict__ fps,      // (B, S)
                float*       __restrict__ out)      // (B, 70, S, 33)
{
    __shared__ int   s_idx[WPB][KTOT];
    __shared__ int   s_hits[WPB][CAP];
    __shared__ float s_stage[WPB][KTOT][HC + 1];

    const int warp = threadIdx.x >> 5;
    const int lane = threadIdx.x & 31;
    const int q    = blockIdx.x * WPB + warp;
    const int b    = q / SS;
    const int s    = q % SS;

    const float qx = new_xyz[q * 3 + 0];
    const float qy = new_xyz[q * 3 + 1];
    const float qz = new_xyz[q * 3 + 2];

    const float R2 = 0.01f;                        // float(0.1*0.1) == 0.01f
    const unsigned lmask = (1u << lane) - 1u;

    // ---- candidate cell ranges (slop absorbs float boundary rounding) ----
    const float SLOP = 0.1f + 1e-6f;
    const int lx = cell1d(__fsub_rn(qx, SLOP)), hx = cell1d(__fadd_rn(qx, SLOP));
    const int ly = cell1d(__fsub_rn(qy, SLOP)), hy = cell1d(__fadd_rn(qy, SLOP));
    const int lz = cell1d(__fsub_rn(qz, SLOP)), hz = cell1d(__fadd_rn(qz, SLOP));

    // ---- fetch ALL (s0,s1) range bounds in parallel (one lane per range) ----
    const int ny = hy - ly + 1;
    const int nr = (hz - lz + 1) * ny;             // <= 9
    int s0r = 0, s1r = 0;
    if (lane < nr) {
        const int cz = lz + lane / ny;
        const int cy = ly + lane % ny;
        const int cbase = b * NCELLS + (cz * GRD + cy) * GRD;
        s0r = g_off[cbase + lx];                   // cells [lx..hx] contiguous
        s1r = g_off[cbase + hx + 1];
    }

    // ---- grid ball query: collect ALL hit ids (unordered) ----
    int M = 0;
    for (int r = 0; r < nr; r++) {
        const int s0 = __shfl_sync(0xffffffffu, s0r, r);
        const int s1 = __shfl_sync(0xffffffffu, s1r, r);
        for (int jj = s0; jj < s1; jj += 32) {     // warp-uniform trip
            const int j = jj + lane;
            const bool act = j < s1;
            const float x = act ? g_gx[j] : 1e9f;
            const float y = act ? g_gy[j] : 1e9f;
            const float z = act ? g_gz[j] : 1e9f;
            const float dx = __fsub_rn(qx, x);
            const float dy = __fsub_rn(qy, y);
            const float dz = __fsub_rn(qz, z);
            // exact JAX order: (dx^2 + dy^2) + dz^2, no FMA contraction
            const float d2 = __fadd_rn(__fadd_rn(__fmul_rn(dx, dx), __fmul_rn(dy, dy)),
                                       __fmul_rn(dz, dz));
            const bool hit = act && (d2 < R2);
            const unsigned m = __ballot_sync(0xffffffffu, hit);
            const int pos = M + __popc(m & lmask);
            if (hit && pos < CAP) s_hits[warp][pos] = g_gid[j];
            M += __popc(m);
        }
    }
    __syncwarp();

    int count;   // total hit count (for cnt/pad logic)
    if (M <= CAP) {
        count = M;
        if (M <= 96) select_hits<3>(s_idx[warp], s_hits[warp], M, lane);      // common case
        else         select_hits<TSEL>(s_idx[warp], s_hits[warp], M, lane);
    } else {
        // ---- fallback (buffer overflow; effectively unreachable): linear scan ----
        const float* __restrict__ bx = g_sx + b * NN;
        const float* __restrict__ by = g_sy + b * NN;
        const float* __restrict__ bz = g_sz + b * NN;
        count = 0;
        for (int base = 0; base < NN; base += 32) {
            const int i = base + lane;
            const float dx = __fsub_rn(qx, bx[i]);
            const float dy = __fsub_rn(qy, by[i]);
            const float dz = __fsub_rn(qz, bz[i]);
            const float d2 = __fadd_rn(__fadd_rn(__fmul_rn(dx, dx), __fmul_rn(dy, dy)),
                                       __fmul_rn(dz, dz));
            const bool hit = d2 < R2;
            const unsigned m = __ballot_sync(0xffffffffu, hit);
            const int pos = count + __popc(m & lmask);
            if (hit && pos < NSAMPLE) s_idx[warp][1 + pos] = i;
            count += __popc(m);
            if (count >= NSAMPLE) break;
        }
    }
    __syncwarp();

    const int cnt = count < NSAMPLE ? count : NSAMPLE;
    const int first = (cnt > 0) ? s_idx[warp][1] : 0;
    if (lane >= cnt) s_idx[warp][1 + lane] = first;   // pad with first hit (or 0)
    if (lane == 0)   s_idx[warp][0] = fps[q];
    __syncwarp();

    // ---- xyz channels (0..5) ----
    const float* __restrict__ bx = g_sx + b * NN;
    const float* __restrict__ by = g_sy + b * NN;
    const float* __restrict__ bz = g_sz + b * NN;
    const size_t CS    = (size_t)SS * KTOT;
    const size_t obase = ((size_t)b * OUTC * SS + s) * KTOT;
    #pragma unroll
    for (int k = lane; k < KTOT; k += 32) {
        const int id = s_idx[warp][k];
        const float x = bx[id];
        const float y = by[id];
        const float z = bz[id];
        const size_t o = obase + k;
        out[o]          = x;
        out[o + CS]     = y;
        out[o + 2 * CS] = z;
        out[o + 3 * CS] = __fsub_rn(x, qx);
        out[o + 4 * CS] = __fsub_rn(y, qy);
        out[o + 5 * CS] = __fsub_rn(z, qz);
    }

    // ---- feature gather + transpose: 2 passes of 32 channels ----
    const float* __restrict__ fb = ftr_t + (size_t)b * NN * CC;
    const size_t fbase = obase + 6 * CS;

    #pragma unroll
    for (int half = 0; half < 2; half++) {
        const int c0 = half * HC;
        #pragma unroll 4
        for (int k = 0; k < KTOT; k++) {
            const int id = s_idx[warp][k];
            s_stage[warp][k][lane] = fb[(size_t)id * CC + c0 + lane];
        }
        __syncwarp();
        #pragma unroll 4
        for (int c = 0; c < HC; c++) {
            const size_t oc = fbase + (size_t)(c0 + c) * CS;
            out[oc + lane] = s_stage[warp][lane][c];
            if (lane == 0) out[oc + 32] = s_stage[warp][32][c];
        }
        __syncwarp();
    }
}

// ---------------------------------------------------------------------------
// Launch: exactly 3 kernels (launch-floor tax was ~20us at 6 kernels).
// ---------------------------------------------------------------------------
extern "C" void kernel_launch(void* const* d_in, const int* in_sizes, int n_in,
                              void* d_out, int out_size) {
    const float* xyz      = (const float*)d_in[0];   // (B, N, 3)
    const float* new_xyz  = (const float*)d_in[1];   // (B, S, 3)
    const float* features = (const float*)d_in[2];   // (B, C, N)
    const int*   fps_idx  = (const int*)  d_in[3];   // (B, S)
    float*       out      = (float*)d_out;           // (B, 70, S, 33)

    float* ftr_t = nullptr;
    cudaGetSymbolAddress((void**)&ftr_t, g_ftr_t);

    prep_kernel<<<TR_BLOCKS + SC_BLOCKS, 1024>>>(features, xyz, ftr_t);
    scan_scatter_kernel<<<SC_BLOCKS, 1024>>>();

    const int nq = BB * SS;                 // 8192
    qag_kernel<<<nq / WPB, WPB * 32>>>(new_xyz, ftr_t, fps_idx, out);
}